// round 10
// baseline (speedup 1.0000x reference)
#include <cuda_runtime.h>
#include <math.h>
#include <stdint.h>

#define N_REGIONS 10
#define HIDDEN    128
#define HEADS     4
#define N_LAYERS  3
#define CHPR      7
#define TOKENS    16384
#define TB        2            // tokens per block
#define NTHREADS  256
typedef unsigned long long u64;

__constant__ int c_nbr_cnt[N_REGIONS] = {5,5,5,3,3,4,3,4,2,2};
__constant__ int c_nbr[N_REGIONS][5] = {
    {0,1,2,3,4},{0,1,2,5,7},{0,1,2,3,7},{0,2,3,0,0},{0,4,5,0,0},
    {1,4,5,6,0},{5,6,9,0,0},{1,2,7,8,0},{7,8,0,0,0},{6,9,0,0,0}
};

// packed GAT weights: g_W4[(l*32+mm)*512 + col] = {W[4mm][col],...,W[4mm+3][col]}
__device__ uint4 g_W4[N_LAYERS * 32 * 512];

__device__ __forceinline__ float gelu_exact(float v) {
    return 0.5f * v * (1.0f + erff(v * 0.70710678118654752f));
}
__device__ __forceinline__ u64 ffma2(u64 a, u64 b, u64 c) {
    u64 d; asm("fma.rn.f32x2 %0, %1, %2, %3;" : "=l"(d) : "l"(a), "l"(b), "l"(c)); return d;
}
__device__ __forceinline__ float hadd2(u64 a) {
    float lo, hi; asm("mov.b64 {%0,%1}, %2;" : "=f"(lo), "=f"(hi) : "l"(a)); return lo + hi;
}
__device__ __forceinline__ u64 pack2f(float lo, float hi) {
    u64 u; asm("mov.b64 %0, {%1,%2};" : "=l"(u) : "f"(lo), "f"(hi)); return u;
}

__global__ void wpack_kernel(const float* __restrict__ W) {
    const int idx = blockIdx.x * 256 + threadIdx.x;    // 0 .. 49151
    const int col = idx & 511;
    const int mm  = (idx >> 9) & 31;
    const int l   = idx >> 14;
    const size_t base = (size_t)l * 65536 + (size_t)(4 * mm) * 512 + col;
    uint4 v;
    v.x = __float_as_uint(W[base]);
    v.y = __float_as_uint(W[base + 512]);
    v.z = __float_as_uint(W[base + 1024]);
    v.w = __float_as_uint(W[base + 1536]);
    g_W4[idx] = v;
}

struct __align__(16) Smem {
    float nodes[TB][N_REGIONS][HIDDEN];            // 10 KB
    float hh[TB][N_REGIONS][HEADS * HIDDEN];       // 40 KB (scalar, for dots)
    ulonglong2 hhp[TB][N_REGIONS][HIDDEN];         // 40 KB: {h0,h1},{h2,h3} per (r,c)
    float alpha[TB][N_REGIONS][N_REGIONS][HEADS];  // 3.2 KB, float4 per (i,j)
    float a[TB][N_REGIONS][HEADS][2];
    float x[TB][72];
    float mu[TB][N_REGIONS];
    float rstd[TB][N_REGIONS];
};

__global__ void __launch_bounds__(NTHREADS, 2) brain_graph_kernel(
    const float* __restrict__ x,
    const float* __restrict__ W_enc,
    const float* __restrict__ b_enc,
    const float* __restrict__ g_enc,
    const float* __restrict__ beta_enc,
    const float* __restrict__ att_src,
    const float* __restrict__ att_dst,
    const float* __restrict__ b_gat,
    float* __restrict__ out)
{
    extern __shared__ Smem S[];
    const int t    = threadIdx.x;        // 0..255
    const int wrp  = t >> 5;             // 0..7
    const int lane = t & 31;
    const int tok0 = blockIdx.x * TB;

    const int gt = t >> 7;               // token within block
    const int c  = t & 127;              // base column / feature

    // ---- load token inputs ----
    if (t < TB * 70) {
        int tt = t / 70, ch = t - tt * 70;
        S->x[tt][ch] = x[(size_t)(tok0 + tt) * 70 + ch];
    }
    __syncthreads();

    // ---- encoders: Linear(7,128) ----
    {
        #pragma unroll
        for (int r = 0; r < N_REGIONS; r++) {
            float acc = b_enc[r * HIDDEN + c];
            #pragma unroll
            for (int ch = 0; ch < CHPR; ch++)
                acc += S->x[gt][r * CHPR + ch] * W_enc[(r * CHPR + ch) * HIDDEN + c];
            S->nodes[gt][r][c] = acc;
        }
    }
    __syncthreads();

    // ---- LayerNorm stats: 20 rows over 8 warps ----
    for (int rl = wrp; rl < TB * N_REGIONS; rl += 8) {
        const int tt = rl / N_REGIONS, r = rl - tt * N_REGIONS;
        float v0 = S->nodes[tt][r][lane];
        float v1 = S->nodes[tt][r][lane + 32];
        float v2 = S->nodes[tt][r][lane + 64];
        float v3 = S->nodes[tt][r][lane + 96];
        float s  = v0 + v1 + v2 + v3;
        float sq = v0*v0 + v1*v1 + v2*v2 + v3*v3;
        #pragma unroll
        for (int o = 16; o > 0; o >>= 1) {
            s  += __shfl_xor_sync(0xffffffffu, s,  o);
            sq += __shfl_xor_sync(0xffffffffu, sq, o);
        }
        if (lane == 0) {
            float mu  = s * (1.0f / HIDDEN);
            float var = sq * (1.0f / HIDDEN) - mu * mu;
            S->mu[tt][r]   = mu;
            S->rstd[tt][r] = rsqrtf(var + 1e-5f);
        }
    }
    __syncthreads();

    // ---- LN affine + GELU; write enc output ----
    {
        const size_t enc_base = (size_t)TOKENS * 1280 + (size_t)(tok0 + gt) * 1280;
        #pragma unroll
        for (int r = 0; r < N_REGIONS; r++) {
            float v = (S->nodes[gt][r][c] - S->mu[gt][r]) * S->rstd[gt][r]
                      * g_enc[r * HIDDEN + c] + beta_enc[r * HIDDEN + c];
            float g = gelu_exact(v);
            S->nodes[gt][r][c] = g;
            out[enc_base + r * HIDDEN + c] = g;
        }
    }
    __syncthreads();

    // ---- GAT layers ----
    for (int l = 0; l < N_LAYERS; l++) {
        // GEMM: hh[gt][r][col] = sum_k nodes[gt][r][k]*W[k][col], cols c+128p
        {
            const uint4* __restrict__ Wb = g_W4 + (size_t)l * 32 * 512 + c;
            u64 acc[N_REGIONS][4];
            #pragma unroll
            for (int r = 0; r < N_REGIONS; r++)
                #pragma unroll
                for (int p = 0; p < 4; p++) acc[r][p] = 0ull;

            uint4 wc[4];
            #pragma unroll
            for (int p = 0; p < 4; p++) wc[p] = __ldg(Wb + 128 * p);

            #pragma unroll 1
            for (int mm = 0; mm < 32; mm++) {
                uint4 wn[4];
                {
                    const int nmm = (mm < 31) ? mm + 1 : 31;
                    #pragma unroll
                    for (int p = 0; p < 4; p++)
                        wn[p] = __ldg(Wb + (size_t)nmm * 512 + 128 * p);
                }
                #pragma unroll
                for (int r = 0; r < N_REGIONS; r++) {
                    const ulonglong2 nd =
                        *reinterpret_cast<const ulonglong2*>(&S->nodes[gt][r][4 * mm]);
                    #pragma unroll
                    for (int p = 0; p < 4; p++) {
                        const ulonglong2 wv = *reinterpret_cast<const ulonglong2*>(&wc[p]);
                        acc[r][p] = ffma2(nd.x, wv.x, acc[r][p]);
                        acc[r][p] = ffma2(nd.y, wv.y, acc[r][p]);
                    }
                }
                #pragma unroll
                for (int p = 0; p < 4; p++) wc[p] = wn[p];
            }
            // epilogue: scalar hh (for dots) + head-packed hhp (for aggregation)
            #pragma unroll
            for (int r = 0; r < N_REGIONS; r++) {
                float v0 = hadd2(acc[r][0]);
                float v1 = hadd2(acc[r][1]);
                float v2 = hadd2(acc[r][2]);
                float v3 = hadd2(acc[r][3]);
                S->hh[gt][r][c]       = v0;
                S->hh[gt][r][c + 128] = v1;
                S->hh[gt][r][c + 256] = v2;
                S->hh[gt][r][c + 384] = v3;
                ulonglong2 pk;
                pk.x = pack2f(v0, v1);
                pk.y = pack2f(v2, v3);
                S->hhp[gt][r][c] = pk;
            }
        }
        __syncthreads();

        // attention scores: TB*80 = 160 length-128 dots over 8 warps
        for (int d = wrp; d < TB * N_REGIONS * HEADS * 2; d += 8) {
            const int tt  = d / 80;
            const int rem = d - tt * 80;
            const int n   = rem >> 3;
            const int h   = (rem >> 1) & 3;
            const int sd  = rem & 1;
            const float* att = (sd ? att_dst : att_src) + l * (HEADS * HIDDEN) + h * HIDDEN;
            float p = 0.0f;
            #pragma unroll
            for (int e = 0; e < HIDDEN; e += 32)
                p += S->hh[tt][n][h * HIDDEN + e + lane] * att[e + lane];
            #pragma unroll
            for (int o = 16; o > 0; o >>= 1)
                p += __shfl_xor_sync(0xffffffffu, p, o);
            if (lane == 0) S->a[tt][n][h][sd] = p;
        }
        __syncthreads();

        // softmax over neighbors: 80 (tt,i,h) units -> alpha4[tt][i][j]
        if (t < TB * N_REGIONS * HEADS) {
            const int tt  = t / 40;
            const int rem = t - tt * 40;
            const int i = rem >> 2, h = rem & 3;
            const int cnt = c_nbr_cnt[i];
            const float ad = S->a[tt][i][h][1];
            float lg[5];
            float mx = -1e30f;
            for (int q = 0; q < cnt; q++) {
                const int j = c_nbr[i][q];
                float v = ad + S->a[tt][j][h][0];
                v = (v >= 0.0f) ? v : 0.2f * v;
                lg[q] = v;
                mx = fmaxf(mx, v);
            }
            float sum = 0.0f;
            for (int q = 0; q < cnt; q++) { lg[q] = expf(lg[q] - mx); sum += lg[q]; }
            const float inv = 1.0f / sum;
            for (int q = 0; q < cnt; q++)
                S->alpha[tt][i][c_nbr[i][q]][h] = lg[q] * inv;
        }
        __syncthreads();

        // aggregation via head-packed math: thread owns (gt,c)
        {
            const float bg = b_gat[l * HIDDEN + c];
            ulonglong2 hv[N_REGIONS];
            #pragma unroll
            for (int j = 0; j < N_REGIONS; j++) hv[j] = S->hhp[gt][j][c];
            #pragma unroll
            for (int i = 0; i < N_REGIONS; i++) {
                u64 s01 = 0ull, s23 = 0ull;
                const int cnt = c_nbr_cnt[i];
                for (int q = 0; q < cnt; q++) {
                    const int j = c_nbr[i][q];
                    const ulonglong2 al =
                        *reinterpret_cast<const ulonglong2*>(&S->alpha[gt][i][j][0]);
                    s01 = ffma2(al.x, hv[j].x, s01);
                    s23 = ffma2(al.y, hv[j].y, s23);
                }
                const float v = (hadd2(s01) + hadd2(s23)) * 0.25f + bg;
                S->nodes[gt][i][c] = gelu_exact(v) + S->nodes[gt][i][c];
            }
        }
        __syncthreads();
    }

    // ---- graph_features output ----
    {
        const size_t gf_base = (size_t)(tok0 + gt) * 1280;
        #pragma unroll
        for (int i = 0; i < N_REGIONS; i++)
            out[gf_base + i * HIDDEN + c] = S->nodes[gt][i][c];
    }
}

extern "C" void kernel_launch(void* const* d_in, const int* in_sizes, int n_in,
                              void* d_out, int out_size) {
    (void)in_sizes; (void)n_in; (void)out_size;
    const float* x        = (const float*)d_in[0];
    const float* W_enc    = (const float*)d_in[1];
    const float* b_enc    = (const float*)d_in[2];
    const float* g_enc    = (const float*)d_in[3];
    const float* beta_enc = (const float*)d_in[4];
    const float* W_gat    = (const float*)d_in[5];
    const float* att_src  = (const float*)d_in[6];
    const float* att_dst  = (const float*)d_in[7];
    const float* b_gat    = (const float*)d_in[8];
    float* out = (float*)d_out;

    static_assert(sizeof(Smem) < 100 * 1024, "smem too big for 2 blocks/SM");
    cudaFuncSetAttribute(brain_graph_kernel,
                         cudaFuncAttributeMaxDynamicSharedMemorySize, (int)sizeof(Smem));

    wpack_kernel<<<(N_LAYERS * 32 * 512) / 256, 256>>>(W_gat);
    brain_graph_kernel<<<TOKENS / TB, NTHREADS, sizeof(Smem)>>>(
        x, W_enc, b_enc, g_enc, beta_enc, att_src, att_dst, b_gat, out);
}

// round 11
// speedup vs baseline: 1.3707x; 1.3707x over previous
#include <cuda_runtime.h>
#include <math.h>
#include <stdint.h>

#define N_REGIONS 10
#define HIDDEN    128
#define HEADS     4
#define N_LAYERS  3
#define CHPR      7
#define TOKENS    16384
#define NTHREADS  128
typedef unsigned long long u64;

__constant__ int c_nbr_cnt[N_REGIONS] = {5,5,5,3,3,4,3,4,2,2};
__constant__ int c_nbr[N_REGIONS][5] = {
    {0,1,2,3,4},{0,1,2,5,7},{0,1,2,3,7},{0,2,3,0,0},{0,4,5,0,0},
    {1,4,5,6,0},{5,6,9,0,0},{1,2,7,8,0},{7,8,0,0,0},{6,9,0,0,0}
};

// packed GAT weights: g_W4[(l*32+mm)*512 + col] = {W[4mm][col],...,W[4mm+3][col]}
__device__ uint4 g_W4[N_LAYERS * 32 * 512];
// folded attention vectors: g_wattT[l][col][k], col = h*2 + sd (sd:0=src,1=dst)
// wattT[l][col][k] = sum_e W[l][k][h][e] * att_{sd}[l][h][e]
__device__ float g_wattT[N_LAYERS * 8 * HIDDEN];

__device__ __forceinline__ float gelu_exact(float v) {
    return 0.5f * v * (1.0f + erff(v * 0.70710678118654752f));
}
__device__ __forceinline__ u64 ffma2(u64 a, u64 b, u64 c) {
    u64 d; asm("fma.rn.f32x2 %0, %1, %2, %3;" : "=l"(d) : "l"(a), "l"(b), "l"(c)); return d;
}
__device__ __forceinline__ float hadd2(u64 a) {
    float lo, hi; asm("mov.b64 {%0,%1}, %2;" : "=f"(lo), "=f"(hi) : "l"(a)); return lo + hi;
}
__device__ __forceinline__ u64 pack2f(float lo, float hi) {
    u64 u; asm("mov.b64 %0, {%1,%2};" : "=l"(u) : "f"(lo), "f"(hi)); return u;
}

__global__ void wpack_kernel(const float* __restrict__ W) {
    const int idx = blockIdx.x * 256 + threadIdx.x;    // 0 .. 49151
    const int col = idx & 511;
    const int mm  = (idx >> 9) & 31;
    const int l   = idx >> 14;
    const size_t base = (size_t)l * 65536 + (size_t)(4 * mm) * 512 + col;
    uint4 v;
    v.x = __float_as_uint(W[base]);
    v.y = __float_as_uint(W[base + 512]);
    v.z = __float_as_uint(W[base + 1024]);
    v.w = __float_as_uint(W[base + 1536]);
    g_W4[idx] = v;
}

__global__ void watt_kernel(const float* __restrict__ W,
                            const float* __restrict__ att_src,
                            const float* __restrict__ att_dst) {
    const int idx = blockIdx.x * 256 + threadIdx.x;    // 0 .. 3071
    if (idx >= N_LAYERS * 8 * HIDDEN) return;
    const int k   = idx & 127;
    const int col = (idx >> 7) & 7;
    const int l   = idx >> 10;
    const int h = col >> 1, sd = col & 1;
    const float* att = (sd ? att_dst : att_src) + (l * HEADS + h) * HIDDEN;
    const float* wrow = W + ((size_t)(l * HIDDEN + k) * HEADS + h) * HIDDEN;
    float s = 0.0f;
    for (int e = 0; e < HIDDEN; e++) s += wrow[e] * att[e];
    g_wattT[idx] = s;
}

struct __align__(16) Smem {
    float nodes[N_REGIONS][HIDDEN];         // 5 KB
    float alpha[N_REGIONS][N_REGIONS][4];   // 1.6 KB, 16B per (i,j)
    float a[N_REGIONS][HEADS][2];           // [n][h][0]=src,[1]=dst
    float xs[72];
    float mu[N_REGIONS], rstd[N_REGIONS];
};

__global__ void __launch_bounds__(NTHREADS, 4) brain_graph_kernel(
    const float* __restrict__ x,
    const float* __restrict__ W_enc,
    const float* __restrict__ b_enc,
    const float* __restrict__ g_enc,
    const float* __restrict__ beta_enc,
    const float* __restrict__ b_gat,
    float* __restrict__ out)
{
    extern __shared__ Smem S[];
    const int t    = threadIdx.x;        // 0..127 = column c / feature
    const int wrp  = t >> 5;
    const int lane = t & 31;
    const int tok  = blockIdx.x;

    // ---- load token input ----
    if (t < 70) S->xs[t] = x[(size_t)tok * 70 + t];
    __syncthreads();

    // ---- encoder Linear(7,128) ----
    #pragma unroll
    for (int r = 0; r < N_REGIONS; r++) {
        float acc = b_enc[r * HIDDEN + t];
        #pragma unroll
        for (int ch = 0; ch < CHPR; ch++)
            acc += S->xs[r * CHPR + ch] * W_enc[(r * CHPR + ch) * HIDDEN + t];
        S->nodes[r][t] = acc;
    }
    __syncthreads();

    // ---- LayerNorm stats (10 rows over 4 warps) ----
    for (int r = wrp; r < N_REGIONS; r += 4) {
        float v0 = S->nodes[r][lane];
        float v1 = S->nodes[r][lane + 32];
        float v2 = S->nodes[r][lane + 64];
        float v3 = S->nodes[r][lane + 96];
        float s  = v0 + v1 + v2 + v3;
        float sq = v0*v0 + v1*v1 + v2*v2 + v3*v3;
        #pragma unroll
        for (int o = 16; o > 0; o >>= 1) {
            s  += __shfl_xor_sync(0xffffffffu, s,  o);
            sq += __shfl_xor_sync(0xffffffffu, sq, o);
        }
        if (lane == 0) {
            float mu  = s * (1.0f / HIDDEN);
            float var = sq * (1.0f / HIDDEN) - mu * mu;
            S->mu[r]   = mu;
            S->rstd[r] = rsqrtf(var + 1e-5f);
        }
    }
    __syncthreads();

    // ---- LN affine + GELU -> nodes + enc output ----
    {
        const size_t enc_base = (size_t)TOKENS * 1280 + (size_t)tok * 1280;
        #pragma unroll
        for (int r = 0; r < N_REGIONS; r++) {
            float v = (S->nodes[r][t] - S->mu[r]) * S->rstd[r]
                      * g_enc[r * HIDDEN + t] + beta_enc[r * HIDDEN + t];
            float g = gelu_exact(v);
            S->nodes[r][t] = g;
            out[enc_base + r * HIDDEN + t] = g;
        }
    }
    __syncthreads();

    // ---- GAT layers ----
    for (int l = 0; l < N_LAYERS; l++) {
        // hv01/hv23[r] = packed per-head GEMM results {h0,h1},{h2,h3} at column t
        u64 hv01[N_REGIONS], hv23[N_REGIONS];

        // ===== interval A: GEMM (acc in regs) + attention dots (nodes x wattT) =====
        {
            // GEMM: acc[r][p] accumulates col = t + 128p (p = head)
            const uint4* __restrict__ Wb = g_W4 + (size_t)l * 32 * 512 + t;
            u64 acc[N_REGIONS][4];
            #pragma unroll
            for (int r = 0; r < N_REGIONS; r++)
                #pragma unroll
                for (int p = 0; p < 4; p++) acc[r][p] = 0ull;

            #pragma unroll 2
            for (int mm = 0; mm < 32; mm++) {
                uint4 wc[4];
                #pragma unroll
                for (int p = 0; p < 4; p++)
                    wc[p] = __ldg(Wb + (size_t)mm * 512 + 128 * p);
                #pragma unroll
                for (int r = 0; r < N_REGIONS; r++) {
                    const ulonglong2 nd =
                        *reinterpret_cast<const ulonglong2*>(&S->nodes[r][4 * mm]);
                    #pragma unroll
                    for (int p = 0; p < 4; p++) {
                        const ulonglong2 wv = *reinterpret_cast<const ulonglong2*>(&wc[p]);
                        acc[r][p] = ffma2(nd.x, wv.x, acc[r][p]);
                        acc[r][p] = ffma2(nd.y, wv.y, acc[r][p]);
                    }
                }
            }
            #pragma unroll
            for (int r = 0; r < N_REGIONS; r++) {
                hv01[r] = pack2f(hadd2(acc[r][0]), hadd2(acc[r][1]));
                hv23[r] = pack2f(hadd2(acc[r][2]), hadd2(acc[r][3]));
            }

            // attention dots: 80 length-128 dots of nodes[n] x wattT[col], 20 per warp
            const float* __restrict__ wt = g_wattT + l * 8 * HIDDEN;
            for (int d = wrp; d < 80; d += 4) {
                const int n = d >> 3, col = d & 7;
                const float* wv = wt + col * HIDDEN;
                float p = S->nodes[n][lane]      * __ldg(wv + lane)
                        + S->nodes[n][lane + 32] * __ldg(wv + lane + 32)
                        + S->nodes[n][lane + 64] * __ldg(wv + lane + 64)
                        + S->nodes[n][lane + 96] * __ldg(wv + lane + 96);
                #pragma unroll
                for (int o = 16; o > 0; o >>= 1)
                    p += __shfl_xor_sync(0xffffffffu, p, o);
                if (lane == 0) S->a[n][col >> 1][col & 1] = p;
            }
        }
        __syncthreads();

        // ===== softmax over neighbors: 40 (i,h) units =====
        if (t < N_REGIONS * HEADS) {
            const int i = t >> 2, h = t & 3;
            const int cnt = c_nbr_cnt[i];
            const float ad = S->a[i][h][1];
            float lg[5];
            float mx = -1e30f;
            for (int q = 0; q < cnt; q++) {
                float v = ad + S->a[c_nbr[i][q]][h][0];
                v = (v >= 0.0f) ? v : 0.2f * v;
                lg[q] = v;
                mx = fmaxf(mx, v);
            }
            float sum = 0.0f;
            for (int q = 0; q < cnt; q++) { lg[q] = expf(lg[q] - mx); sum += lg[q]; }
            const float inv = 1.0f / sum;
            for (int q = 0; q < cnt; q++)
                S->alpha[i][c_nbr[i][q]][h] = lg[q] * inv;
        }
        __syncthreads();

        // ===== aggregation from registers + epilogue =====
        {
            const float bg = b_gat[l * HIDDEN + t];
            float newn[N_REGIONS];
            #pragma unroll
            for (int i = 0; i < N_REGIONS; i++) {
                u64 s01 = 0ull, s23 = 0ull;
                const int cnt = c_nbr_cnt[i];
                for (int q = 0; q < cnt; q++) {
                    const int j = c_nbr[i][q];
                    const ulonglong2 al =
                        *reinterpret_cast<const ulonglong2*>(&S->alpha[i][j][0]);
                    s01 = ffma2(al.x, hv01[j], s01);
                    s23 = ffma2(al.y, hv23[j], s23);
                }
                const float v = (hadd2(s01) + hadd2(s23)) * 0.25f + bg;
                newn[i] = gelu_exact(v) + S->nodes[i][t];
            }
            // thread exclusively owns column t of nodes
            #pragma unroll
            for (int i = 0; i < N_REGIONS; i++) S->nodes[i][t] = newn[i];
        }
        __syncthreads();
    }

    // ---- graph_features output ----
    {
        const size_t gf_base = (size_t)tok * 1280;
        #pragma unroll
        for (int i = 0; i < N_REGIONS; i++)
            out[gf_base + i * HIDDEN + t] = S->nodes[i][t];
    }
}

extern "C" void kernel_launch(void* const* d_in, const int* in_sizes, int n_in,
                              void* d_out, int out_size) {
    (void)in_sizes; (void)n_in; (void)out_size;
    const float* x        = (const float*)d_in[0];
    const float* W_enc    = (const float*)d_in[1];
    const float* b_enc    = (const float*)d_in[2];
    const float* g_enc    = (const float*)d_in[3];
    const float* beta_enc = (const float*)d_in[4];
    const float* W_gat    = (const float*)d_in[5];
    const float* att_src  = (const float*)d_in[6];
    const float* att_dst  = (const float*)d_in[7];
    const float* b_gat    = (const float*)d_in[8];
    float* out = (float*)d_out;

    static_assert(sizeof(Smem) < 9 * 1024, "smem unexpectedly large");
    cudaFuncSetAttribute(brain_graph_kernel,
                         cudaFuncAttributeMaxDynamicSharedMemorySize, (int)sizeof(Smem));

    wpack_kernel<<<(N_LAYERS * 32 * 512) / 256, 256>>>(W_gat);
    watt_kernel<<<(N_LAYERS * 8 * HIDDEN + 255) / 256, 256>>>(W_gat, att_src, att_dst);
    brain_graph_kernel<<<TOKENS, NTHREADS, sizeof(Smem)>>>(
        x, W_enc, b_enc, g_enc, beta_enc, b_gat, out);
}

// round 12
// speedup vs baseline: 1.7835x; 1.3012x over previous
#include <cuda_runtime.h>
#include <math.h>
#include <stdint.h>

#define N_REGIONS 10
#define HIDDEN    128
#define HEADS     4
#define N_LAYERS  3
#define CHPR      7
#define TOKENS    16384
#define TW        6                          // tokens per CTA, M = 64 rows
#define NCTAS     ((TOKENS + TW - 1) / TW)   // 2731
#define NT        128                        // 4 warps

typedef unsigned long long u64;
typedef uint32_t u32;

__constant__ int c_nbr_cnt[N_REGIONS] = {5,5,5,3,3,4,3,4,2,2};
__constant__ int c_nbr[N_REGIONS][5] = {
    {0,1,2,3,4},{0,1,2,5,7},{0,1,2,3,7},{0,2,3,0,0},{0,4,5,0,0},
    {1,4,5,6,0},{5,6,9,0,0},{1,2,7,8,0},{7,8,0,0,0},{6,9,0,0,0}
};
__constant__ float c_att_src[N_LAYERS * HEADS * HIDDEN];
__constant__ float c_att_dst[N_LAYERS * HEADS * HIDDEN];

// fragment-major packed W (tf32): idx = ((l*4+h)*256 + kt*16 + nt)*32 + lane
// b0 = W[k=kt*8+tq][e=nt*8+g], b1 = W[k=kt*8+tq+4][e]   (verified in R7/R8)
__device__ u64 g_Wpack[N_LAYERS * HEADS * 16 * 16 * 32];

__device__ __forceinline__ float gelu_exact(float v) {
    return 0.5f * v * (1.0f + erff(v * 0.70710678118654752f));
}
__device__ __forceinline__ u32 cvt_tf32(float f) {
    u32 r; asm("cvt.rna.tf32.f32 %0, %1;" : "=r"(r) : "f"(f)); return r;
}
__device__ __forceinline__ void mma_tf32(float c[4], const u32 a[4], u32 b0, u32 b1) {
    asm volatile(
        "mma.sync.aligned.m16n8k8.row.col.f32.tf32.tf32.f32 "
        "{%0,%1,%2,%3}, {%4,%5,%6,%7}, {%8,%9}, {%0,%1,%2,%3};"
        : "+f"(c[0]), "+f"(c[1]), "+f"(c[2]), "+f"(c[3])
        : "r"(a[0]), "r"(a[1]), "r"(a[2]), "r"(a[3]), "r"(b0), "r"(b1));
}

__global__ void wpack_kernel(const float* __restrict__ W) {
    const int idx  = blockIdx.x * 256 + threadIdx.x;   // 98304 total
    const int lane = idx & 31;
    const int nt   = (idx >> 5) & 15;
    const int kt   = (idx >> 9) & 15;
    const int h    = (idx >> 13) & 3;
    const int l    = idx >> 15;
    const int tq = lane & 3, g = lane >> 2;
    const int k0 = kt * 8 + tq;
    const int e  = nt * 8 + g;
    const u32 b0 = cvt_tf32(W[((size_t)(l * 128 + k0)     * 4 + h) * 128 + e]);
    const u32 b1 = cvt_tf32(W[((size_t)(l * 128 + k0 + 4) * 4 + h) * 128 + e]);
    g_Wpack[idx] = ((u64)b1 << 32) | (u64)b0;
}

struct __align__(16) Smem {
    float nodes[64][132];        // rows 60..63 zero pad
    float hh[64][132];           // per-head GEMM result (B source for MMA2)
    float alphaH[6][10][10];     // alpha for current head
    float aatt[64][8];           // [row][2h]=a_src, [2h+1]=a_dst
    float xs[TW * 70];
    float mu[64], rstd[64];
};

__global__ void __launch_bounds__(NT, 2) brain_mma_kernel(
    const float* __restrict__ x,
    const float* __restrict__ W_enc,
    const float* __restrict__ b_enc,
    const float* __restrict__ g_enc,
    const float* __restrict__ beta_enc,
    const float* __restrict__ b_gat,
    float* __restrict__ out)
{
    extern __shared__ Smem S[];
    const int t = threadIdx.x, w = t >> 5, lane = t & 31;
    const int g = lane >> 2, tq = lane & 3;
    const int tok0 = blockIdx.x * TW;
    const int r0 = w * 16 + g;          // strip rows r0, r0+8
    const int r8 = r0 + 8;

    // ---- zero pad rows, load inputs ----
    for (int i = t; i < 4 * 132; i += NT) S->nodes[60 + i / 132][i % 132] = 0.0f;
    for (int i = t; i < TW * 70; i += NT) {
        const int tt = i / 70, tok = tok0 + tt;
        S->xs[i] = (tok < TOKENS) ? x[(size_t)tok * 70 + (i - tt * 70)] : 0.0f;
    }
    __syncthreads();

    // ---- encoder Linear(7,128), col = t ----
    #pragma unroll 1
    for (int r = 0; r < N_REGIONS; r++) {
        float wv[CHPR];
        #pragma unroll
        for (int c = 0; c < CHPR; c++) wv[c] = W_enc[(r * CHPR + c) * 128 + t];
        const float bb = b_enc[r * 128 + t];
        #pragma unroll
        for (int tt = 0; tt < TW; tt++) {
            float acc = bb;
            #pragma unroll
            for (int c = 0; c < CHPR; c++) acc += S->xs[tt * 70 + r * CHPR + c] * wv[c];
            S->nodes[tt * 10 + r][t] = acc;
        }
    }
    __syncthreads();

    // ---- LayerNorm stats: rows 0..59 over 4 warps ----
    for (int row = w; row < 60; row += 4) {
        float v0 = S->nodes[row][lane];
        float v1 = S->nodes[row][lane + 32];
        float v2 = S->nodes[row][lane + 64];
        float v3 = S->nodes[row][lane + 96];
        float s  = v0 + v1 + v2 + v3;
        float sq = v0*v0 + v1*v1 + v2*v2 + v3*v3;
        #pragma unroll
        for (int o = 16; o > 0; o >>= 1) {
            s  += __shfl_xor_sync(0xffffffffu, s, o);
            sq += __shfl_xor_sync(0xffffffffu, sq, o);
        }
        if (lane == 0) {
            const float m = s * (1.0f / 128.0f);
            S->mu[row]   = m;
            S->rstd[row] = rsqrtf(sq * (1.0f / 128.0f) - m * m + 1e-5f);
        }
    }
    __syncthreads();

    // ---- LN affine + GELU -> nodes + enc output ----
    #pragma unroll 1
    for (int r = 0; r < N_REGIONS; r++) {
        const float ge = g_enc[r * 128 + t], be = beta_enc[r * 128 + t];
        #pragma unroll
        for (int tt = 0; tt < TW; tt++) {
            const int row = tt * 10 + r;
            float v = (S->nodes[row][t] - S->mu[row]) * S->rstd[row] * ge + be;
            const float gv = gelu_exact(v);
            S->nodes[row][t] = gv;
            if (tok0 + tt < TOKENS)
                out[(size_t)TOKENS * 1280 + (size_t)(tok0 + tt) * 1280 + r * 128 + t] = gv;
        }
    }
    __syncthreads();

    // row->token mapping (for MMA2 alpha fragments & epilogue)
    const int tokr  = r0 / 10, ir  = r0 - 10 * tokr;
    const int tokr8 = r8 / 10, ir8 = r8 - 10 * tokr8;
    const int vr  = (r0 < 60) ? tokr  : -1;
    const int vr8 = (r8 < 60) ? tokr8 : -1;

    // ---- GAT layers ----
    #pragma unroll 1
    for (int l = 0; l < N_LAYERS; l++) {
        float c2[16][4];
        #pragma unroll
        for (int nt = 0; nt < 16; nt++)
            #pragma unroll
            for (int ii = 0; ii < 4; ii++) c2[nt][ii] = 0.0f;

        #pragma unroll 1
        for (int h = 0; h < HEADS; h++) {
            // ===== MMA1: hh = nodes @ W_{l,h}; dot partials fused =====
            float asl = 0.0f, adl = 0.0f, ash = 0.0f, adh = 0.0f;
            const u64* __restrict__ bp = g_Wpack + (size_t)((l * 4 + h) * 256) * 32 + lane;
            #pragma unroll 1
            for (int half = 0; half < 2; half++) {
                const u64* __restrict__ bph = bp + half * 8 * 32;
                float c1[8][4];
                #pragma unroll
                for (int nt = 0; nt < 8; nt++)
                    #pragma unroll
                    for (int ii = 0; ii < 4; ii++) c1[nt][ii] = 0.0f;

                u64 bw[8];
                #pragma unroll
                for (int nt = 0; nt < 8; nt++) bw[nt] = __ldg(bph + nt * 32);

                #pragma unroll 1
                for (int kt = 0; kt < 16; kt++) {
                    u32 a[4];
                    a[0] = cvt_tf32(S->nodes[r0][kt * 8 + tq]);
                    a[1] = cvt_tf32(S->nodes[r8][kt * 8 + tq]);
                    a[2] = cvt_tf32(S->nodes[r0][kt * 8 + tq + 4]);
                    a[3] = cvt_tf32(S->nodes[r8][kt * 8 + tq + 4]);
                    u64 bn[8];
                    const int nkt = (kt < 15) ? kt + 1 : 15;
                    #pragma unroll
                    for (int nt = 0; nt < 8; nt++)
                        bn[nt] = __ldg(bph + (nkt * 16 + nt) * 32);
                    #pragma unroll
                    for (int nt = 0; nt < 8; nt++)
                        mma_tf32(c1[nt], a, (u32)bw[nt], (u32)(bw[nt] >> 32));
                    #pragma unroll
                    for (int nt = 0; nt < 8; nt++) bw[nt] = bn[nt];
                }
                // store hh + dot partials
                #pragma unroll
                for (int nt = 0; nt < 8; nt++) {
                    const int col0 = (half * 8 + nt) * 8 + 2 * tq;
                    *reinterpret_cast<float2*>(&S->hh[r0][col0]) = make_float2(c1[nt][0], c1[nt][1]);
                    *reinterpret_cast<float2*>(&S->hh[r8][col0]) = make_float2(c1[nt][2], c1[nt][3]);
                    const float s0 = c_att_src[(l * 4 + h) * 128 + col0];
                    const float s1 = c_att_src[(l * 4 + h) * 128 + col0 + 1];
                    const float d0 = c_att_dst[(l * 4 + h) * 128 + col0];
                    const float d1 = c_att_dst[(l * 4 + h) * 128 + col0 + 1];
                    asl += c1[nt][0] * s0 + c1[nt][1] * s1;
                    adl += c1[nt][0] * d0 + c1[nt][1] * d1;
                    ash += c1[nt][2] * s0 + c1[nt][3] * s1;
                    adh += c1[nt][2] * d0 + c1[nt][3] * d1;
                }
            }
            // reduce dots over the quad (lanes 4g..4g+3)
            asl += __shfl_xor_sync(0xffffffffu, asl, 1); asl += __shfl_xor_sync(0xffffffffu, asl, 2);
            adl += __shfl_xor_sync(0xffffffffu, adl, 1); adl += __shfl_xor_sync(0xffffffffu, adl, 2);
            ash += __shfl_xor_sync(0xffffffffu, ash, 1); ash += __shfl_xor_sync(0xffffffffu, ash, 2);
            adh += __shfl_xor_sync(0xffffffffu, adh, 1); adh += __shfl_xor_sync(0xffffffffu, adh, 2);
            if (tq == 0) {
                *reinterpret_cast<float2*>(&S->aatt[r0][2 * h]) = make_float2(asl, adl);
                *reinterpret_cast<float2*>(&S->aatt[r8][2 * h]) = make_float2(ash, adh);
            }
            __syncthreads();

            // ===== softmax for head h -> alphaH =====
            if (t < 60) {
                const int tok = t / 10, i = t - 10 * tok;
                const float ad = S->aatt[t][2 * h + 1];
                float row10[10];
                #pragma unroll
                for (int j = 0; j < 10; j++) row10[j] = 0.0f;
                const int cnt = c_nbr_cnt[i];
                float lg[5];
                float mx = -1e30f;
                for (int q = 0; q < cnt; q++) {
                    float v = ad + S->aatt[tok * 10 + c_nbr[i][q]][2 * h];
                    v = (v >= 0.0f) ? v : 0.2f * v;
                    lg[q] = v;
                    mx = fmaxf(mx, v);
                }
                float sum = 0.0f;
                for (int q = 0; q < cnt; q++) { lg[q] = expf(lg[q] - mx); sum += lg[q]; }
                const float inv = 1.0f / sum;
                for (int q = 0; q < cnt; q++) row10[c_nbr[i][q]] = lg[q] * inv;
                #pragma unroll
                for (int j = 0; j < 10; j++) S->alphaH[tok][i][j] = row10[j];
            }
            __syncthreads();

            // ===== MMA2: c2 += alpha_h (block-diag) @ hh_h =====
            #pragma unroll 1
            for (int kt = 0; kt < 8; kt++) {
                const int k1 = kt * 8 + tq, k2 = k1 + 4;
                const int tc1 = k1 / 10, j1 = k1 - 10 * tc1;
                const int tc2 = k2 / 10, j2 = k2 - 10 * tc2;
                u32 a[4];
                a[0] = (vr  == tc1) ? cvt_tf32(S->alphaH[tc1][ir ][j1]) : 0u;
                a[1] = (vr8 == tc1) ? cvt_tf32(S->alphaH[tc1][ir8][j1]) : 0u;
                a[2] = (vr  == tc2) ? cvt_tf32(S->alphaH[tc2][ir ][j2]) : 0u;
                a[3] = (vr8 == tc2) ? cvt_tf32(S->alphaH[tc2][ir8][j2]) : 0u;
                #pragma unroll
                for (int nt = 0; nt < 16; nt++) {
                    const u32 b0 = cvt_tf32(S->hh[kt * 8 + tq][nt * 8 + g]);
                    const u32 b1 = cvt_tf32(S->hh[kt * 8 + tq + 4][nt * 8 + g]);
                    mma_tf32(c2[nt], a, b0, b1);
                }
            }
            __syncthreads();   // hh/alphaH free for next head
        } // heads

        // ===== epilogue: mean heads + bias + GELU + residual =====
        {
            const float* __restrict__ bgp = b_gat + l * 128;
            #pragma unroll
            for (int nt = 0; nt < 16; nt++) {
                const int col0 = nt * 8 + 2 * tq;
                const float b0 = __ldg(bgp + col0), b1 = __ldg(bgp + col0 + 1);
                if (r0 < 60) {
                    const float n0 = gelu_exact(c2[nt][0] * 0.25f + b0) + S->nodes[r0][col0];
                    const float n1 = gelu_exact(c2[nt][1] * 0.25f + b1) + S->nodes[r0][col0 + 1];
                    *reinterpret_cast<float2*>(&S->nodes[r0][col0]) = make_float2(n0, n1);
                    if (l == N_LAYERS - 1 && tok0 + tokr < TOKENS)
                        *reinterpret_cast<float2*>(&out[(size_t)(tok0 + tokr) * 1280 + ir * 128 + col0])
                            = make_float2(n0, n1);
                }
                if (r8 < 60) {
                    const float n2 = gelu_exact(c2[nt][2] * 0.25f + b0) + S->nodes[r8][col0];
                    const float n3 = gelu_exact(c2[nt][3] * 0.25f + b1) + S->nodes[r8][col0 + 1];
                    *reinterpret_cast<float2*>(&S->nodes[r8][col0]) = make_float2(n2, n3);
                    if (l == N_LAYERS - 1 && tok0 + tokr8 < TOKENS)
                        *reinterpret_cast<float2*>(&out[(size_t)(tok0 + tokr8) * 1280 + ir8 * 128 + col0])
                            = make_float2(n2, n3);
                }
            }
        }
        __syncthreads();
    } // layers
}

extern "C" void kernel_launch(void* const* d_in, const int* in_sizes, int n_in,
                              void* d_out, int out_size) {
    (void)in_sizes; (void)n_in; (void)out_size;
    const float* x        = (const float*)d_in[0];
    const float* W_enc    = (const float*)d_in[1];
    const float* b_enc    = (const float*)d_in[2];
    const float* g_enc    = (const float*)d_in[3];
    const float* beta_enc = (const float*)d_in[4];
    const float* W_gat    = (const float*)d_in[5];
    const float* att_src  = (const float*)d_in[6];
    const float* att_dst  = (const float*)d_in[7];
    const float* b_gat    = (const float*)d_in[8];
    float* out = (float*)d_out;

    static_assert(sizeof(Smem) <= 110 * 1024, "smem too big for 2 CTAs/SM");
    cudaFuncSetAttribute(brain_mma_kernel,
                         cudaFuncAttributeMaxDynamicSharedMemorySize, (int)sizeof(Smem));

    cudaMemcpyToSymbolAsync(c_att_src, att_src, N_LAYERS * HEADS * HIDDEN * sizeof(float),
                            0, cudaMemcpyDeviceToDevice);
    cudaMemcpyToSymbolAsync(c_att_dst, att_dst, N_LAYERS * HEADS * HIDDEN * sizeof(float),
                            0, cudaMemcpyDeviceToDevice);
    wpack_kernel<<<(N_LAYERS * HEADS * 16 * 16 * 32) / 256, 256>>>(W_gat);
    brain_mma_kernel<<<NCTAS, NT, sizeof(Smem)>>>(
        x, W_enc, b_enc, g_enc, beta_enc, b_gat, out);
}